// round 9
// baseline (speedup 1.0000x reference)
#include <cuda_runtime.h>
#include <cstdint>

#define NTOT 12544   // 16 * 784 flattened spatial*batch
#define HWSZ 784
#define WD   28

// ---------------- scratch (device globals; no allocation allowed) ----------
__device__ float g_xT [512 * NTOT];
__device__ float g_t3 [512 * NTOT];
__device__ float g_t1a[128 * NTOT]; __device__ float g_t1b[128 * NTOT];
__device__ float g_t1 [128 * NTOT];
__device__ float g_u1a[128 * NTOT]; __device__ float g_u1b[128 * NTOT];
__device__ float g_u1 [128 * NTOT];
__device__ float g_t2a[128 * NTOT]; __device__ float g_t2b[128 * NTOT];
__device__ float g_t2 [128 * NTOT];
__device__ float g_u2a[128 * NTOT]; __device__ float g_u2b[128 * NTOT];
__device__ float g_u2 [128 * NTOT];
__device__ float g_q1T [512 * 128];   // quantized w1s, k-major
__device__ float g_w1aT[128 * 128];   // w1a k-major, NEGATED
__device__ float g_q2T [1152 * 128];
__device__ float g_w2aT[1152 * 128];  // negated
__device__ float g_q3T [128 * 512];
__device__ float g_w3aT[512 * 512];   // negated
__device__ float g_inv1[128], g_bias1[128], g_inv2[128], g_bias2[128];

template<int ID>
__device__ __forceinline__ float* gbuf(float* rt) {
    if constexpr (ID == 0) return g_xT;
    else if constexpr (ID == 1) return g_t3;
    else if constexpr (ID == 2) return g_t1a;
    else if constexpr (ID == 3) return g_t1b;
    else if constexpr (ID == 4) return g_t1;
    else if constexpr (ID == 5) return g_u1a;
    else if constexpr (ID == 6) return g_u1b;
    else if constexpr (ID == 7) return g_u1;
    else if constexpr (ID == 8) return g_t2a;
    else if constexpr (ID == 9) return g_t2b;
    else if constexpr (ID == 10) return g_t2;
    else if constexpr (ID == 11) return g_u2a;
    else if constexpr (ID == 12) return g_u2b;
    else if constexpr (ID == 13) return g_u2;
    else if constexpr (ID == 14) return g_q1T;
    else if constexpr (ID == 15) return g_w1aT;
    else if constexpr (ID == 16) return g_q2T;
    else if constexpr (ID == 17) return g_w2aT;
    else if constexpr (ID == 18) return g_q3T;
    else if constexpr (ID == 19) return g_w3aT;
    else return rt;
}

// ---- weight prep (quantize/negate + k-major transpose), one kernel --------
__device__ __forceinline__ void wp_one(const float* src, float* dst,
                                       int i, int M, int K, int quant, int neg) {
    int m = i / K, k = i - m * K;
    float w = src[i];
    float q = w;
    if (quant) {
        float a = fabsf(w) + 1e-8f;
        q = copysignf(exp2f(rintf(log2f(a))), w);
        if (w == 0.0f) q = 0.0f;   // jnp.sign(0) == 0
    }
    if (neg) q = -q;
    dst[k * M + m] = q;
}

__global__ void wprep_all(const float* __restrict__ w1s, const float* __restrict__ w1a,
                          const float* __restrict__ w2s, const float* __restrict__ w2a,
                          const float* __restrict__ w3s, const float* __restrict__ w3a) {
    int gid = blockIdx.x * blockDim.x + threadIdx.x;
    if (gid < 65536)                 wp_one(w1s, g_q1T,  gid,          128, 512,  1, 0);
    else if (gid < 81920)            wp_one(w1a, g_w1aT, gid - 65536,  128, 128,  0, 1);
    else if (gid < 229376)           wp_one(w2s, g_q2T,  gid - 81920,  128, 1152, 1, 0);
    else if (gid < 376832)           wp_one(w2a, g_w2aT, gid - 229376, 128, 1152, 0, 1);
    else if (gid < 442368)           wp_one(w3s, g_q3T,  gid - 376832, 512, 128,  1, 0);
    else if (gid < 704512)           wp_one(w3a, g_w3aT, gid - 442368, 512, 512,  0, 1);
}

__global__ void bnprep(const float* g1, const float* b1, const float* m1, const float* v1,
                       const float* g2, const float* b2, const float* m2, const float* v2) {
    int i = threadIdx.x;
    if (i < 128) {
        float inv = g1[i] * rsqrtf(v1[i] + 1e-5f);
        g_inv1[i] = inv; g_bias1[i] = b1[i] - m1[i] * inv;
        float inv2 = g2[i] * rsqrtf(v2[i] + 1e-5f);
        g_inv2[i] = inv2; g_bias2[i] = b2[i] - m2[i] * inv2;
    }
}

// -------- x: NCHW -> [c][b*784+hw] ----------------------------------------
__global__ void transpose_x(const float* __restrict__ x) {
    int i = blockIdx.x * blockDim.x + threadIdx.x;
    if (i >= 512 * (NTOT / 4)) return;
    int c  = i / (NTOT / 4);
    int r  = i - c * (NTOT / 4);
    int n  = r * 4;
    int b  = n / HWSZ;
    int hw = n - b * HWSZ;
    float4 v = ((const float4*)x)[((b * 512 + c) * HWSZ + hw) >> 2];
    ((float4*)g_xT)[i] = v;
}

// -------- partial combines -------------------------------------------------
// csum: Y = X0 + X1 (shift-conv partials)
template<int X0ID, int X1ID, int YID>
__global__ void csum() {
    int i = blockIdx.x * 256 + threadIdx.x;   // float4 index, 128*NTOT/4 total
    const float4* a = (const float4*)gbuf<X0ID>(nullptr);
    const float4* b = (const float4*)gbuf<X1ID>(nullptr);
    float4* y = (float4*)gbuf<YID>(nullptr);
    float4 va = a[i], vb = b[i];
    y[i] = make_float4(va.x + vb.x, va.y + vb.y, va.z + vb.z, va.w + vb.w);
}
// cbn: Y = relu(bias[c] - inv[c] * (X0 + X1))  (adder partials + BN + ReLU)
template<int X0ID, int X1ID, int YID, int BNSEL>
__global__ void cbn() {
    int i = blockIdx.x * 256 + threadIdx.x;
    int c = (i * 4) / NTOT;
    float inv  = (BNSEL == 1) ? g_inv1[c]  : g_inv2[c];
    float bias = (BNSEL == 1) ? g_bias1[c] : g_bias2[c];
    const float4* a = (const float4*)gbuf<X0ID>(nullptr);
    const float4* b = (const float4*)gbuf<X1ID>(nullptr);
    float4* y = (float4*)gbuf<YID>(nullptr);
    float4 va = a[i], vb = b[i];
    y[i] = make_float4(fmaxf(fmaf(va.x + vb.x, -inv, bias), 0.0f),
                       fmaxf(fmaf(va.y + vb.y, -inv, bias), 0.0f),
                       fmaxf(fmaf(va.z + vb.z, -inv, bias), 0.0f),
                       fmaxf(fmaf(va.w + vb.w, -inv, bias), 0.0f));
}

// ---- cp.async helpers -----------------------------------------------------
__device__ __forceinline__ uint32_t s2u(const void* p) {
    uint32_t a;
    asm("{ .reg .u64 t; cvta.to.shared.u64 t, %1; cvt.u32.u64 %0, t; }"
        : "=r"(a) : "l"(p));
    return a;
}
__device__ __forceinline__ void cpa16(uint32_t d, const float* s) {
    asm volatile("cp.async.ca.shared.global [%0], [%1], 16;" :: "r"(d), "l"(s));
}
__device__ __forceinline__ void cpa4z(uint32_t d, const float* s, int sz) {
    asm volatile("cp.async.ca.shared.global [%0], [%1], 4, %2;"
                 :: "r"(d), "l"(s), "r"(sz));
}
__device__ __forceinline__ void cp_commit() {
    asm volatile("cp.async.commit_group;");
}
template<int N>
__device__ __forceinline__ void cp_wait() {
    asm volatile("cp.async.wait_group %0;" :: "n"(N));
}

// ---------------------------------------------------------------------------
// GEMM-shaped kernel, S-stage cp.async pipeline, split-K via blockIdx.z.
// BN=128, NT=128 threads, TM x 8 thread tile. kbase = z*K; z selects Y0/Y1.
//   MODE 0: acc += a*b   MODE 1: acc += |b-a| (A negated)
//   CONV 0: 1x1 fill (16B cp.async)  CONV 1: implicit 3x3, zfill halo (BK=18)
//   EPI 0: raw acc store to Y[z]   EPI 2: relu(bn3(-acc)+resid) NCHW store
// ---------------------------------------------------------------------------
template<int BM, int TM, int BK, int S, int MODE, int CONV, int EPI,
         int WID, int XID, int Y0ID, int Y1ID>
__global__ void __launch_bounds__(128)
gx(float* Yrt, int Mtot, int K,
   const float* __restrict__ bg, const float* __restrict__ bb,
   const float* __restrict__ bm, const float* __restrict__ bv,
   const float* __restrict__ resid)
{
    constexpr int BN = 128, NT = 128;
    static_assert((BM / TM) * 16 == NT, "tile/threads mismatch");
    constexpr int AF4 = BK * BM / 4;
    constexpr int AU  = (AF4 + NT - 1) / NT;
    constexpr int BU  = CONV ? 1 : (BK * BN / 4 / NT);
    const float* Wt = gbuf<WID>(nullptr);
    const float* X  = gbuf<XID>(nullptr);
    int zz = blockIdx.z;
    int kbase = zz * K;
    float* Y = zz ? gbuf<Y1ID>(Yrt) : gbuf<Y0ID>(Yrt);

    __shared__ __align__(16) float As[S][BK * BM];
    __shared__ __align__(16) float Bs[S][BK * BN];

    int tid = threadIdx.x;
    int tx  = tid % 16;
    int ty  = tid / 16;
    int m0  = blockIdx.y * BM;
    int n0  = blockIdx.x * BN;

    // conv geometry: loop-invariant halo predicates -> cp.async zfill sizes
    int cn = n0 + tid;
    int coff[9]; int csz[9];
    if (CONV) {
        int cw = cn % WD;
        int ch = (cn / WD) % WD;
#pragma unroll
        for (int q = 0; q < 9; q++) {
            const int r = q / 3, s = q % 3;
            int hh = ch + r - 1, ww = cw + s - 1;
            bool ok = (hh >= 0 && hh < WD && ww >= 0 && ww < WD);
            coff[q] = ok ? (r - 1) * WD + (s - 1) : 0;
            csz[q]  = ok ? 4 : 0;
        }
    }

    const uint32_t AsU = s2u(&As[0][0]);
    const uint32_t BsU = s2u(&Bs[0][0]);
    constexpr int ASTAGE = BK * BM * 4;
    constexpr int BSTAGE = BK * BN * 4;

    auto fill = [&](int t) {
        int st = t % S;
        int k0 = kbase + t * BK;
#pragma unroll
        for (int u = 0; u < AU; u++) {
            int v = tid + u * NT;
            if (AF4 % NT == 0 || v < AF4) {
                int kk = v / (BM / 4), mq = v - kk * (BM / 4);
                cpa16(AsU + st * ASTAGE + (kk * BM + mq * 4) * 4,
                      &Wt[(long)(k0 + kk) * Mtot + m0 + mq * 4]);
            }
        }
        if (CONV == 0) {
#pragma unroll
            for (int u = 0; u < BU; u++) {
                int v = tid + u * NT;
                int kk = v / (BN / 4), nq = v - kk * (BN / 4);
                cpa16(BsU + st * BSTAGE + (kk * BN + nq * 4) * 4,
                      &X[(long)(k0 + kk) * NTOT + n0 + nq * 4]);
            }
        } else {
            int c0 = k0 / 9;
#pragma unroll
            for (int half = 0; half < 2; half++) {
                const float* base = &X[(long)(c0 + half) * NTOT + cn];
#pragma unroll
                for (int q = 0; q < 9; q++)
                    cpa4z(BsU + st * BSTAGE + ((half * 9 + q) * BN + tid) * 4,
                          base + coff[q], csz[q]);
            }
        }
    };

    unsigned long long acc2[TM][4];
#pragma unroll
    for (int i = 0; i < TM; i++)
#pragma unroll
        for (int j = 0; j < 4; j++) acc2[i][j] = 0ULL;

    int T = K / BK;
#pragma unroll
    for (int p = 0; p < S - 1; p++) {
        if (p < T) fill(p);
        cp_commit();
    }

    for (int t = 0; t < T; t++) {
        cp_wait<S - 2>();
        __syncthreads();
        int tf = t + S - 1;
        if (tf < T) fill(tf);
        cp_commit();

        int st = t % S;
#pragma unroll
        for (int kk = 0; kk < BK; kk++) {
            float a[TM];
            *(float4*)&a[0] = *(const float4*)&As[st][kk * BM + ty * TM];
            if constexpr (TM == 8)
                *(float4*)&a[4] = *(const float4*)&As[st][kk * BM + ty * TM + 4];
            unsigned long long ad[TM];
#pragma unroll
            for (int i = 0; i < TM; i++)
                asm("mov.b64 %0, {%1, %1};" : "=l"(ad[i]) : "f"(a[i]));
            unsigned long long b2[4];
            {
                ulonglong2 p0 = *(const ulonglong2*)&Bs[st][kk * BN + tx * 8];
                ulonglong2 p1 = *(const ulonglong2*)&Bs[st][kk * BN + tx * 8 + 4];
                b2[0] = p0.x; b2[1] = p0.y; b2[2] = p1.x; b2[3] = p1.y;
            }
#pragma unroll
            for (int i = 0; i < TM; i++)
#pragma unroll
                for (int jp = 0; jp < 4; jp++) {
                    if (MODE == 0) {
                        asm("fma.rn.f32x2 %0, %1, %2, %0;"
                            : "+l"(acc2[i][jp]) : "l"(ad[i]), "l"(b2[jp]));
                    } else {
                        unsigned long long d;
                        asm("add.rn.f32x2 %0, %1, %2;"
                            : "=l"(d) : "l"(b2[jp]), "l"(ad[i]));
                        d &= 0x7FFFFFFF7FFFFFFFULL;
                        asm("add.rn.f32x2 %0, %0, %1;"
                            : "+l"(acc2[i][jp]) : "l"(d));
                    }
                }
        }
    }
    cp_wait<0>();

    // ---- unpack + epilogue ----
    float accf[TM][8];
#pragma unroll
    for (int i = 0; i < TM; i++)
#pragma unroll
        for (int jp = 0; jp < 4; jp++)
            asm("mov.b64 {%0, %1}, %2;"
                : "=f"(accf[i][2*jp]), "=f"(accf[i][2*jp+1]) : "l"(acc2[i][jp]));

#pragma unroll
    for (int i = 0; i < TM; i++) {
        int m = m0 + ty * TM + i;
        if (EPI == 2) {
            float inv  = bg[m] * rsqrtf(bv[m] + 1e-5f);
            float bias = bb[m] - bm[m] * inv;
#pragma unroll
            for (int j = 0; j < 8; j++) {
                int n   = n0 + tx * 8 + j;
                int b_  = n / HWSZ;
                int hw  = n - b_ * HWSZ;
                int idx = (b_ * 512 + m) * HWSZ + hw;
                float v = fmaf(accf[i][j], -inv, bias) + resid[idx];
                Y[idx] = fmaxf(v, 0.0f);
            }
        } else {
            int base = m * NTOT + n0 + tx * 8;
            *(float4*)&Y[base]     = make_float4(accf[i][0], accf[i][1],
                                                 accf[i][2], accf[i][3]);
            *(float4*)&Y[base + 4] = make_float4(accf[i][4], accf[i][5],
                                                 accf[i][6], accf[i][7]);
        }
    }
}

// ---------------------------------------------------------------------------
extern "C" void kernel_launch(void* const* d_in, const int* in_sizes, int n_in,
                              void* d_out, int out_size) {
    const float* x   = (const float*)d_in[0];
    const float* w1s = (const float*)d_in[1];
    const float* w1a = (const float*)d_in[2];
    const float* w2s = (const float*)d_in[3];
    const float* w2a = (const float*)d_in[4];
    const float* w3s = (const float*)d_in[5];
    const float* w3a = (const float*)d_in[6];
    const float* g1 = (const float*)d_in[7],  *b1 = (const float*)d_in[8];
    const float* m1 = (const float*)d_in[9],  *v1 = (const float*)d_in[10];
    const float* g2 = (const float*)d_in[11], *b2 = (const float*)d_in[12];
    const float* m2 = (const float*)d_in[13], *v2 = (const float*)d_in[14];
    const float* g3 = (const float*)d_in[15], *b3 = (const float*)d_in[16];
    const float* m3 = (const float*)d_in[17], *v3 = (const float*)d_in[18];
    float* out = (float*)d_out;

    wprep_all<<<(704512 + 255) / 256, 256>>>(w1s, w1a, w2s, w2a, w3s, w3a);
    bnprep<<<1, 128>>>(g1, b1, m1, v1, g2, b2, m2, v2);
    transpose_x<<<(512 * (NTOT / 4) + 255) / 256, 256>>>(x);

    dim3 gz (98, 4, 2);   // M=128 stages, BM=32, split-K co-resident
    dim3 gbg(98, 8, 1);   // M=512 stages, BM=64
    const int CGRID = 128 * (NTOT / 4) / 256;   // combine grid (1568)

    // stage 1 shift: K=512 split 2x256 -> t1a/t1b; combine -> t1
    gx<32,4,16,4, 0,0,0, 14,0, 2,3><<<gz,128>>>(
        nullptr, 128, 256, nullptr, nullptr, nullptr, nullptr, nullptr);
    csum<2,3,4><<<CGRID,256>>>();
    // stage 1 adder: K=128 split 2x64 -> u1a/u1b; combine+BN1+ReLU -> u1
    gx<32,4,16,4, 1,0,0, 15,4, 5,6><<<gz,128>>>(
        nullptr, 128, 64, nullptr, nullptr, nullptr, nullptr, nullptr);
    cbn<5,6,7,1><<<CGRID,256>>>();
    // stage 2 shift (3x3): K=1152 split 2x576 -> t2a/t2b; combine -> t2
    gx<32,4,18,4, 0,1,0, 16,7, 8,9><<<gz,128>>>(
        nullptr, 128, 576, nullptr, nullptr, nullptr, nullptr, nullptr);
    csum<8,9,10><<<CGRID,256>>>();
    // stage 2 adder (3x3): K=1152 split 2x576 -> u2a/u2b; combine+BN2+ReLU -> u2
    gx<32,4,18,4, 1,1,0, 17,10, 11,12><<<gz,128>>>(
        nullptr, 128, 576, nullptr, nullptr, nullptr, nullptr, nullptr);
    cbn<11,12,13,2><<<CGRID,256>>>();
    // stage 3 shift: M=512, K=128 -> t3
    gx<64,8,16,3, 0,0,0, 18,13, 1,1><<<gbg,128>>>(
        nullptr, 512, 128, nullptr, nullptr, nullptr, nullptr, nullptr);
    // stage 3 adder: K=512, bn3 + resid + relu -> out (NCHW)
    gx<64,8,16,3, 1,0,2, 19,1, -1,-1><<<gbg,128>>>(
        out, 512, 512, g3, b3, m3, v3, x);
}

// round 10
// speedup vs baseline: 1.0201x; 1.0201x over previous
#include <cuda_runtime.h>
#include <cstdint>

#define NTOT 12544   // 16 * 784 flattened spatial*batch
#define HWSZ 784
#define WD   28

// ---------------- scratch (device globals; no allocation allowed) ----------
__device__ float g_xT [512 * NTOT];
__device__ float g_A  [512 * NTOT];   // t1 then t3
__device__ float g_B  [128 * NTOT];   // u1 then u2
__device__ float g_C  [128 * NTOT];   // t2
__device__ float g_q1T [512 * 128];   // quantized w1s, k-major
__device__ float g_w1aT[128 * 128];   // w1a k-major, NEGATED
__device__ float g_q2T [1152 * 128];
__device__ float g_w2aT[1152 * 128];  // negated
__device__ float g_q3T [128 * 512];
__device__ float g_w3aT[512 * 512];   // negated

template<int ID>
__device__ __forceinline__ float* gbuf(float* rt) {
    if constexpr (ID == 0) return g_xT;
    else if constexpr (ID == 1) return g_A;
    else if constexpr (ID == 2) return g_B;
    else if constexpr (ID == 3) return g_C;
    else if constexpr (ID == 4) return g_q1T;
    else if constexpr (ID == 5) return g_w1aT;
    else if constexpr (ID == 6) return g_q2T;
    else if constexpr (ID == 7) return g_w2aT;
    else if constexpr (ID == 8) return g_q3T;
    else if constexpr (ID == 9) return g_w3aT;
    else return rt;
}

// ---- weight prep (quantize/negate + k-major transpose), one kernel --------
__device__ __forceinline__ void wp_one(const float* src, float* dst,
                                       int i, int M, int K, int quant, int neg) {
    int m = i / K, k = i - m * K;
    float w = src[i];
    float q = w;
    if (quant) {
        float a = fabsf(w) + 1e-8f;
        q = copysignf(exp2f(rintf(log2f(a))), w);
        if (w == 0.0f) q = 0.0f;   // jnp.sign(0) == 0
    }
    if (neg) q = -q;
    dst[k * M + m] = q;
}

__global__ void wprep_all(const float* __restrict__ w1s, const float* __restrict__ w1a,
                          const float* __restrict__ w2s, const float* __restrict__ w2a,
                          const float* __restrict__ w3s, const float* __restrict__ w3a) {
    int gid = blockIdx.x * blockDim.x + threadIdx.x;
    if (gid < 65536)                 wp_one(w1s, g_q1T,  gid,          128, 512,  1, 0);
    else if (gid < 81920)            wp_one(w1a, g_w1aT, gid - 65536,  128, 128,  0, 1);
    else if (gid < 229376)           wp_one(w2s, g_q2T,  gid - 81920,  128, 1152, 1, 0);
    else if (gid < 376832)           wp_one(w2a, g_w2aT, gid - 229376, 128, 1152, 0, 1);
    else if (gid < 442368)           wp_one(w3s, g_q3T,  gid - 376832, 512, 128,  1, 0);
    else if (gid < 704512)           wp_one(w3a, g_w3aT, gid - 442368, 512, 512,  0, 1);
}

// -------- x: NCHW -> [c][b*784+hw] ----------------------------------------
__global__ void transpose_x(const float* __restrict__ x) {
    int i = blockIdx.x * blockDim.x + threadIdx.x;
    if (i >= 512 * (NTOT / 4)) return;
    int c  = i / (NTOT / 4);
    int r  = i - c * (NTOT / 4);
    int n  = r * 4;
    int b  = n / HWSZ;
    int hw = n - b * HWSZ;
    float4 v = ((const float4*)x)[((b * 512 + c) * HWSZ + hw) >> 2];
    ((float4*)g_xT)[i] = v;
}

// ---- cp.async helpers -----------------------------------------------------
__device__ __forceinline__ uint32_t s2u(const void* p) {
    uint32_t a;
    asm("{ .reg .u64 t; cvta.to.shared.u64 t, %1; cvt.u32.u64 %0, t; }"
        : "=r"(a) : "l"(p));
    return a;
}
__device__ __forceinline__ void cpa16(uint32_t d, const float* s) {
    asm volatile("cp.async.ca.shared.global [%0], [%1], 16;" :: "r"(d), "l"(s));
}
__device__ __forceinline__ void cpa4z(uint32_t d, const float* s, int sz) {
    asm volatile("cp.async.ca.shared.global [%0], [%1], 4, %2;"
                 :: "r"(d), "l"(s), "r"(sz));
}
__device__ __forceinline__ void cp_commit() {
    asm volatile("cp.async.commit_group;");
}
template<int N>
__device__ __forceinline__ void cp_wait() {
    asm volatile("cp.async.wait_group %0;" :: "n"(N));
}

// ---------------------------------------------------------------------------
// GEMM-shaped kernel: S-stage cp.async smem pipeline PLUS register
// double-buffering of the kk loop (load kk+1 operands while computing kk,
// so the LDS->use distance is a full kk of math).
//   MODE 0: acc += a*b   MODE 1: acc += |b-a| (A negated; epilogue negates)
//   CONV 0: 1x1 fill (16B cp.async)  CONV 1: implicit 3x3, zfill halo (BK=18)
//   EPI 0: raw store  EPI 1: relu(bn(-acc))  EPI 2: relu(bn3(-acc)+resid) NCHW
// ---------------------------------------------------------------------------
template<int BM, int TM, int BK, int S, int MODE, int CONV, int EPI,
         int WID, int XID, int YID>
__global__ void __launch_bounds__(128)
gx(float* Yrt, int Mtot, int K,
   const float* __restrict__ bg, const float* __restrict__ bb,
   const float* __restrict__ bm, const float* __restrict__ bv,
   const float* __restrict__ resid)
{
    constexpr int BN = 128, NT = 128;
    static_assert((BM / TM) * 16 == NT, "tile/threads mismatch");
    constexpr int AF4 = BK * BM / 4;
    constexpr int AU  = (AF4 + NT - 1) / NT;
    constexpr int BU  = CONV ? 1 : (BK * BN / 4 / NT);
    const float* Wt = gbuf<WID>(nullptr);
    const float* X  = gbuf<XID>(nullptr);
    float*       Y  = gbuf<YID>(Yrt);

    __shared__ __align__(16) float As[S][BK * BM];
    __shared__ __align__(16) float Bs[S][BK * BN];

    int tid = threadIdx.x;
    int tx  = tid % 16;
    int ty  = tid / 16;
    int m0  = blockIdx.y * BM;
    int n0  = blockIdx.x * BN;

    // conv geometry: loop-invariant halo predicates -> cp.async zfill sizes
    int cn = n0 + tid;
    int coff[9]; int csz[9];
    if (CONV) {
        int cw = cn % WD;
        int ch = (cn / WD) % WD;
#pragma unroll
        for (int q = 0; q < 9; q++) {
            const int r = q / 3, s = q % 3;
            int hh = ch + r - 1, ww = cw + s - 1;
            bool ok = (hh >= 0 && hh < WD && ww >= 0 && ww < WD);
            coff[q] = ok ? (r - 1) * WD + (s - 1) : 0;
            csz[q]  = ok ? 4 : 0;
        }
    }

    const uint32_t AsU = s2u(&As[0][0]);
    const uint32_t BsU = s2u(&Bs[0][0]);
    constexpr int ASTAGE = BK * BM * 4;
    constexpr int BSTAGE = BK * BN * 4;

    auto fill = [&](int t) {
        int st = t % S;
        int k0 = t * BK;
#pragma unroll
        for (int u = 0; u < AU; u++) {
            int v = tid + u * NT;
            if (AF4 % NT == 0 || v < AF4) {
                int kk = v / (BM / 4), mq = v - kk * (BM / 4);
                cpa16(AsU + st * ASTAGE + (kk * BM + mq * 4) * 4,
                      &Wt[(long)(k0 + kk) * Mtot + m0 + mq * 4]);
            }
        }
        if (CONV == 0) {
#pragma unroll
            for (int u = 0; u < BU; u++) {
                int v = tid + u * NT;
                int kk = v / (BN / 4), nq = v - kk * (BN / 4);
                cpa16(BsU + st * BSTAGE + (kk * BN + nq * 4) * 4,
                      &X[(long)(k0 + kk) * NTOT + n0 + nq * 4]);
            }
        } else {
            int c0 = k0 / 9;
#pragma unroll
            for (int half = 0; half < 2; half++) {
                const float* base = &X[(long)(c0 + half) * NTOT + cn];
#pragma unroll
                for (int q = 0; q < 9; q++)
                    cpa4z(BsU + st * BSTAGE + ((half * 9 + q) * BN + tid) * 4,
                          base + coff[q], csz[q]);
            }
        }
    };

    unsigned long long acc2[TM][4];
#pragma unroll
    for (int i = 0; i < TM; i++)
#pragma unroll
        for (int j = 0; j < 4; j++) acc2[i][j] = 0ULL;

    int T = K / BK;
#pragma unroll
    for (int p = 0; p < S - 1; p++) {
        if (p < T) fill(p);
        cp_commit();
    }

    for (int t = 0; t < T; t++) {
        cp_wait<S - 2>();
        __syncthreads();
        int tf = t + S - 1;
        if (tf < T) fill(tf);
        cp_commit();

        int st = t % S;

        // ---- register double-buffered kk loop ----
        float af[2][TM];
        unsigned long long b2r[2][4];
        auto ldreg = [&](int kk, int sl) {
            *(float4*)&af[sl][0] = *(const float4*)&As[st][kk * BM + ty * TM];
            if constexpr (TM == 8)
                *(float4*)&af[sl][4] =
                    *(const float4*)&As[st][kk * BM + ty * TM + 4];
            ulonglong2 p0 = *(const ulonglong2*)&Bs[st][kk * BN + tx * 8];
            ulonglong2 p1 = *(const ulonglong2*)&Bs[st][kk * BN + tx * 8 + 4];
            b2r[sl][0] = p0.x; b2r[sl][1] = p0.y;
            b2r[sl][2] = p1.x; b2r[sl][3] = p1.y;
        };
        ldreg(0, 0);
#pragma unroll
        for (int kk = 0; kk < BK; kk++) {
            int cur = kk & 1;
            if (kk + 1 < BK) ldreg(kk + 1, cur ^ 1);
            unsigned long long ad[TM];
#pragma unroll
            for (int i = 0; i < TM; i++)
                asm("mov.b64 %0, {%1, %1};" : "=l"(ad[i]) : "f"(af[cur][i]));
#pragma unroll
            for (int i = 0; i < TM; i++)
#pragma unroll
                for (int jp = 0; jp < 4; jp++) {
                    if (MODE == 0) {
                        asm("fma.rn.f32x2 %0, %1, %2, %0;"
                            : "+l"(acc2[i][jp]) : "l"(ad[i]), "l"(b2r[cur][jp]));
                    } else {
                        unsigned long long d;
                        asm("add.rn.f32x2 %0, %1, %2;"
                            : "=l"(d) : "l"(b2r[cur][jp]), "l"(ad[i]));
                        d &= 0x7FFFFFFF7FFFFFFFULL;
                        asm("add.rn.f32x2 %0, %0, %1;"
                            : "+l"(acc2[i][jp]) : "l"(d));
                    }
                }
        }
    }
    cp_wait<0>();

    // ---- unpack + epilogue ----
    float accf[TM][8];
#pragma unroll
    for (int i = 0; i < TM; i++)
#pragma unroll
        for (int jp = 0; jp < 4; jp++)
            asm("mov.b64 {%0, %1}, %2;"
                : "=f"(accf[i][2*jp]), "=f"(accf[i][2*jp+1]) : "l"(acc2[i][jp]));

#pragma unroll
    for (int i = 0; i < TM; i++) {
        int m = m0 + ty * TM + i;
        float inv = 1.0f, bias = 0.0f;
        if (EPI >= 1) {
            inv  = bg[m] * rsqrtf(bv[m] + 1e-5f);
            bias = bb[m] - bm[m] * inv;
        }
        if (EPI == 2) {
#pragma unroll
            for (int j = 0; j < 8; j++) {
                int n   = n0 + tx * 8 + j;
                int b_  = n / HWSZ;
                int hw  = n - b_ * HWSZ;
                int idx = (b_ * 512 + m) * HWSZ + hw;
                float v = fmaf(accf[i][j], -inv, bias) + resid[idx];
                Y[idx] = fmaxf(v, 0.0f);
            }
        } else {
            float o[8];
#pragma unroll
            for (int j = 0; j < 8; j++) {
                float v = (MODE == 0) ? accf[i][j] : -accf[i][j];
                if (EPI == 1) v = fmaxf(fmaf(v, inv, bias), 0.0f);
                o[j] = v;
            }
            int base = m * NTOT + n0 + tx * 8;
            *(float4*)&Y[base]     = make_float4(o[0], o[1], o[2], o[3]);
            *(float4*)&Y[base + 4] = make_float4(o[4], o[5], o[6], o[7]);
        }
    }
}

// ---------------------------------------------------------------------------
extern "C" void kernel_launch(void* const* d_in, const int* in_sizes, int n_in,
                              void* d_out, int out_size) {
    const float* x   = (const float*)d_in[0];
    const float* w1s = (const float*)d_in[1];
    const float* w1a = (const float*)d_in[2];
    const float* w2s = (const float*)d_in[3];
    const float* w2a = (const float*)d_in[4];
    const float* w3s = (const float*)d_in[5];
    const float* w3a = (const float*)d_in[6];
    const float* g1 = (const float*)d_in[7],  *b1 = (const float*)d_in[8];
    const float* m1 = (const float*)d_in[9],  *v1 = (const float*)d_in[10];
    const float* g2 = (const float*)d_in[11], *b2 = (const float*)d_in[12];
    const float* m2 = (const float*)d_in[13], *v2 = (const float*)d_in[14];
    const float* g3 = (const float*)d_in[15], *b3 = (const float*)d_in[16];
    const float* m3 = (const float*)d_in[17], *v3 = (const float*)d_in[18];
    float* out = (float*)d_out;

    wprep_all<<<(704512 + 255) / 256, 256>>>(w1s, w1a, w2s, w2a, w3s, w3a);
    transpose_x<<<(512 * (NTOT / 4) + 255) / 256, 256>>>(x);

    dim3 gsm(98, 4);   // M=128 stages, BM=32
    dim3 gbg(98, 8);   // M=512 stages, BM=64

    // stage 1: shift 1x1 (K=512) -> t1 (g_A)
    gx<32,4,16,4, 0,0,0, 4,0,1><<<gsm,128>>>(
        nullptr, 128, 512, nullptr, nullptr, nullptr, nullptr, nullptr);
    // stage 1: adder 1x1 + BN1 + ReLU -> u1 (g_B)
    gx<32,4,16,4, 1,0,1, 5,1,2><<<gsm,128>>>(
        nullptr, 128, 128, g1, b1, m1, v1, nullptr);

    // stage 2: shift 3x3 (K=1152, BK=18) -> t2 (g_C)
    gx<32,4,18,4, 0,1,0, 6,2,3><<<gsm,128>>>(
        nullptr, 128, 1152, nullptr, nullptr, nullptr, nullptr, nullptr);
    // stage 2: adder 3x3 + BN2 + ReLU -> u2 (g_B)
    gx<32,4,18,4, 1,1,1, 7,3,2><<<gsm,128>>>(
        nullptr, 128, 1152, g2, b2, m2, v2, nullptr);

    // stage 3: shift 1x1 (M=512, K=128) -> t3 (g_A)
    gx<64,8,16,3, 0,0,0, 8,2,1><<<gbg,128>>>(
        nullptr, 512, 128, nullptr, nullptr, nullptr, nullptr, nullptr);
    // stage 3: adder 1x1 (K=512) + BN3 + resid + ReLU -> out (NCHW)
    gx<64,8,16,3, 1,0,2, 9,1,-1><<<gbg,128>>>(
        out, 512, 512, g3, b3, m3, v3, x);
}

// round 13
// speedup vs baseline: 1.2601x; 1.2353x over previous
#include <cuda_runtime.h>
#include <cuda_bf16.h>
#include <cstdint>

#define NTOT 12544   // 16 * 784 flattened spatial*batch
#define HWSZ 784
#define WD   28

// ---------------- scratch (device globals; no allocation allowed) ----------
__device__ float g_A  [512 * NTOT];   // t1 then t3
__device__ float g_B  [128 * NTOT];   // u1 then u2
__device__ float g_C  [128 * NTOT];   // t2
__device__ float g_w1aT[128 * 128];   // w1a k-major, NEGATED
__device__ float g_w2aT[1152 * 128];  // w2a k-major (c*9+rs order), NEGATED
__device__ float g_w3aT[512 * 512];   // negated
__device__ __nv_bfloat16 g_w1bf[128 * 512];    // quantized w1s [m][k]
__device__ __nv_bfloat16 g_w2bf[128 * 1152];   // quantized w2s [m][rs*128+c]
__device__ __nv_bfloat16 g_w3bf[512 * 128];    // quantized w3s [m][k]
__device__ __nv_bfloat16 g_xth[NTOT * 512];    // x transposed [n][c], hi/lo
__device__ __nv_bfloat16 g_xtl[NTOT * 512];
__device__ __nv_bfloat16 g_uth[NTOT * 128];    // u1 then u2 transposed
__device__ __nv_bfloat16 g_utl[NTOT * 128];

template<int ID>
__device__ __forceinline__ float* gbuf(float* rt) {
    if constexpr (ID == 1) return g_A;
    else if constexpr (ID == 2) return g_B;
    else if constexpr (ID == 3) return g_C;
    else if constexpr (ID == 5) return g_w1aT;
    else if constexpr (ID == 7) return g_w2aT;
    else if constexpr (ID == 9) return g_w3aT;
    else return rt;
}

// ---- weight prep ----------------------------------------------------------
__device__ __forceinline__ float wquant(float w) {
    float a = fabsf(w) + 1e-8f;
    float q = copysignf(exp2f(rintf(log2f(a))), w);
    if (w == 0.0f) q = 0.0f;   // jnp.sign(0) == 0
    return q;
}
__device__ __forceinline__ void wp_t(const float* src, float* dst,
                                     int i, int M, int K) {
    int m = i / K, k = i - m * K;
    dst[k * M + m] = -src[i];
}

__global__ void wprep_all(const float* __restrict__ w1s, const float* __restrict__ w1a,
                          const float* __restrict__ w2s, const float* __restrict__ w2a,
                          const float* __restrict__ w3s, const float* __restrict__ w3a) {
    int gid = blockIdx.x * blockDim.x + threadIdx.x;
    if (gid < 65536) {                       // w1s -> bf16 [m][k] quantized
        g_w1bf[gid] = __float2bfloat16(wquant(w1s[gid]));
    } else if (gid < 81920) {                // w1a -> k-major negated f32
        wp_t(w1a, g_w1aT, gid - 65536, 128, 128);
    } else if (gid < 229376) {               // w2s -> bf16 [m][rs*128+c] quantized
        int i = gid - 81920;
        int m = i / 1152, rem = i - m * 1152;
        int c = rem / 9, rs = rem - c * 9;
        g_w2bf[m * 1152 + rs * 128 + c] = __float2bfloat16(wquant(w2s[i]));
    } else if (gid < 376832) {               // w2a -> k-major negated (c*9+rs)
        wp_t(w2a, g_w2aT, gid - 229376, 128, 1152);
    } else if (gid < 442368) {               // w3s -> bf16 [m][k] quantized
        g_w3bf[gid - 376832] = __float2bfloat16(wquant(w3s[gid - 376832]));
    } else if (gid < 704512) {               // w3a -> k-major negated
        wp_t(w3a, g_w3aT, gid - 442368, 512, 512);
    }
}

// ---- transpose + bf16 hi/lo split ------------------------------------------
// x NCHW [b][512][hw] -> xt planes [n=b*784+hw][c]
__global__ void tsplit_x(const float* __restrict__ x) {
    __shared__ float sm[32][33];
    int b = blockIdx.z, c0 = blockIdx.y * 32, hw0 = blockIdx.x * 32;
    int tx = threadIdx.x, ty = threadIdx.y;
#pragma unroll
    for (int i = 0; i < 4; i++) {
        int hw = hw0 + tx;
        if (hw < HWSZ)
            sm[ty + i * 8][tx] = x[((long)b * 512 + c0 + ty + i * 8) * HWSZ + hw];
    }
    __syncthreads();
#pragma unroll
    for (int i = 0; i < 4; i++) {
        int hw = hw0 + ty + i * 8;
        if (hw < HWSZ) {
            long n = (long)b * HWSZ + hw;
            float v = sm[tx][ty + i * 8];
            __nv_bfloat16 h = __float2bfloat16(v);
            g_xth[n * 512 + c0 + tx] = h;
            g_xtl[n * 512 + c0 + tx] = __float2bfloat16(v - __bfloat162float(h));
        }
    }
}
// u [C=128][NTOT] f32 (g_B) -> ut planes [n][128]
__global__ void tsplit_u() {
    __shared__ float sm[32][33];
    int n0 = blockIdx.x * 32, c0 = blockIdx.y * 32;
    int tx = threadIdx.x, ty = threadIdx.y;
#pragma unroll
    for (int i = 0; i < 4; i++)
        sm[ty + i * 8][tx] = g_B[(long)(c0 + ty + i * 8) * NTOT + n0 + tx];
    __syncthreads();
#pragma unroll
    for (int i = 0; i < 4; i++) {
        long n = n0 + ty + i * 8;
        float v = sm[tx][ty + i * 8];
        __nv_bfloat16 h = __float2bfloat16(v);
        g_uth[n * 128 + c0 + tx] = h;
        g_utl[n * 128 + c0 + tx] = __float2bfloat16(v - __bfloat162float(h));
    }
}

// ---- asm helpers ----------------------------------------------------------
__device__ __forceinline__ uint32_t s2u(const void* p) {
    uint32_t a;
    asm("{ .reg .u64 t; cvta.to.shared.u64 t, %1; cvt.u32.u64 %0, t; }"
        : "=r"(a) : "l"(p));
    return a;
}
__device__ __forceinline__ void cpa16(uint32_t d, const void* s) {
    asm volatile("cp.async.ca.shared.global [%0], [%1], 16;" :: "r"(d), "l"(s));
}
__device__ __forceinline__ void cpa16z(uint32_t d, const void* s, int sz) {
    asm volatile("cp.async.ca.shared.global [%0], [%1], 16, %2;"
                 :: "r"(d), "l"(s), "r"(sz));
}
__device__ __forceinline__ void cpa4z(uint32_t d, const float* s, int sz) {
    asm volatile("cp.async.ca.shared.global [%0], [%1], 4, %2;"
                 :: "r"(d), "l"(s), "r"(sz));
}
__device__ __forceinline__ void cp_commit() {
    asm volatile("cp.async.commit_group;");
}
template<int N>
__device__ __forceinline__ void cp_wait() {
    asm volatile("cp.async.wait_group %0;" :: "n"(N));
}
__device__ __forceinline__ void ldmx4(uint32_t& r0, uint32_t& r1, uint32_t& r2,
                                      uint32_t& r3, uint32_t a) {
    asm volatile("ldmatrix.sync.aligned.m8n8.x4.shared.b16 {%0,%1,%2,%3}, [%4];"
                 : "=r"(r0), "=r"(r1), "=r"(r2), "=r"(r3) : "r"(a));
}
__device__ __forceinline__ void mma_bf16(float* c, const uint32_t* a,
                                         const uint32_t* b) {
    asm volatile(
        "mma.sync.aligned.m16n8k16.row.col.f32.bf16.bf16.f32 "
        "{%0,%1,%2,%3}, {%4,%5,%6,%7}, {%8,%9}, {%0,%1,%2,%3};"
        : "+f"(c[0]), "+f"(c[1]), "+f"(c[2]), "+f"(c[3])
        : "r"(a[0]), "r"(a[1]), "r"(a[2]), "r"(a[3]), "r"(b[0]), "r"(b[1]));
}

#define SWZ(x) ((x) ^ (((x) >> 3) & 0x70))

// ---------------------------------------------------------------------------
// Shift-conv GEMM on tensor cores (legacy mma.sync, bf16 hi/lo, fp32 accum).
// Block: 128 threads (4 warps, 2x2 of 32x32 warp tiles), tile 64m x 64n.
// K processed in 64-element chunks (128B smem rows, SW128), 3-stage cp.async.
// CONV=0: B rows from Xt[n][CH] at k-offset. CONV=1: implicit 3x3, K order
// rs-major (k = rs*128 + c), B row = Xt[n + off(rs)][chalf*64 ...], zfill halo.
// ---------------------------------------------------------------------------
template<int CONV>
__global__ void __launch_bounds__(128)
mma_shift(const __nv_bfloat16* __restrict__ W,
          const __nv_bfloat16* __restrict__ X0,
          const __nv_bfloat16* __restrict__ X1,
          float* __restrict__ Y, int Mtot, int Ktot, int CH, int nchunks)
{
    __shared__ __align__(128) char sm[3][16384];
    uint32_t smU = s2u(sm);

    int tid = threadIdx.x;
    int lane = tid & 31, wid = tid >> 5;
    int m0 = blockIdx.y * 64, n0 = blockIdx.x * 64;
    int wm = (wid & 1) * 32, wn = (wid >> 1) * 32;

    // fill-thread geometry: thread owns row = tid/2, half = tid&1
    int frow = tid >> 1, fhalf = tid & 1;
    int fn = n0 + frow;
    int fw = fn % WD, fh = (fn / WD) % WD;

    auto fill = [&](int t) {
        int st = t % 3;
        uint32_t ab = smU + st * 16384;
        uint32_t bb = ab + 8192;
        long aoff; const __nv_bfloat16* Xp; long boff; int bsz = 16;
        if (CONV == 0) {
            int per = Ktot >> 6;
            int p = t / per, ks = t - p * per;
            Xp = p ? X1 : X0;
            aoff = (long)(m0 + frow) * Ktot + ks * 64 + fhalf * 32;
            boff = (long)fn * CH + ks * 64 + fhalf * 32;
        } else {
            int seg = t, p = 0;
            if (seg >= 18) { p = 1; seg -= 18; }
            Xp = p ? X1 : X0;
            int rs = seg >> 1;
            aoff = (long)(m0 + frow) * 1152 + seg * 64 + fhalf * 32;
            int r = rs / 3, s = rs - r * 3;
            int hh = fh + r - 1, ww = fw + s - 1;
            bool ok = (hh >= 0 && hh < WD && ww >= 0 && ww < WD);
            bsz = ok ? 16 : 0;
            long nn = ok ? (fn + (r - 1) * WD + (s - 1)) : fn;
            boff = nn * 128 + (seg & 1) * 64 + fhalf * 32;
        }
#pragma unroll
        for (int q = 0; q < 4; q++) {
            int d = frow * 128 + fhalf * 64 + q * 16;
            cpa16(ab + SWZ(d), W + aoff + q * 8);
            cpa16z(bb + SWZ(d), Xp + boff + q * 8, bsz);
        }
    };

    float acc[2][4][4];
#pragma unroll
    for (int i = 0; i < 2; i++)
#pragma unroll
        for (int j = 0; j < 4; j++)
#pragma unroll
            for (int q = 0; q < 4; q++) acc[i][j][q] = 0.0f;

#pragma unroll
    for (int p = 0; p < 2; p++) {
        if (p < nchunks) fill(p);
        cp_commit();
    }

    for (int t = 0; t < nchunks; t++) {
        cp_wait<1>();
        __syncthreads();
        if (t + 2 < nchunks) fill(t + 2);
        cp_commit();

        int st = t % 3;
        uint32_t ab = smU + st * 16384;
        uint32_t bb = ab + 8192;
#pragma unroll
        for (int k16 = 0; k16 < 4; k16++) {
            int kb = k16 * 32;
            uint32_t a[2][4];
#pragma unroll
            for (int mi = 0; mi < 2; mi++) {
                uint32_t ad = ab + SWZ((wm + mi * 16 + (lane & 15)) * 128 +
                                       kb + (lane >> 4) * 16);
                ldmx4(a[mi][0], a[mi][1], a[mi][2], a[mi][3], ad);
            }
            uint32_t b[4][2];
#pragma unroll
            for (int nj = 0; nj < 2; nj++) {
                uint32_t bd = bb + SWZ((wn + nj * 16 + (lane & 7) +
                                        ((lane & 16) ? 8 : 0)) * 128 +
                                       kb + ((lane & 8) ? 16 : 0));
                uint32_t r0, r1, r2, r3;
                ldmx4(r0, r1, r2, r3, bd);
                b[nj * 2][0] = r0;  b[nj * 2][1] = r1;
                b[nj * 2 + 1][0] = r2;  b[nj * 2 + 1][1] = r3;
            }
#pragma unroll
            for (int mi = 0; mi < 2; mi++)
#pragma unroll
                for (int nf = 0; nf < 4; nf++)
                    mma_bf16(acc[mi][nf], a[mi], b[nf]);
        }
    }
    cp_wait<0>();

    // epilogue: D frag (m16n8): c0,c1 at (row=lane/4, col=2(lane%4)); c2,c3 row+8
#pragma unroll
    for (int mi = 0; mi < 2; mi++) {
#pragma unroll
        for (int nf = 0; nf < 4; nf++) {
            long mr = m0 + wm + mi * 16 + (lane >> 2);
            long col = n0 + wn + nf * 8 + 2 * (lane & 3);
            *(float2*)&Y[mr * NTOT + col] =
                make_float2(acc[mi][nf][0], acc[mi][nf][1]);
            *(float2*)&Y[(mr + 8) * NTOT + col] =
                make_float2(acc[mi][nf][2], acc[mi][nf][3]);
        }
    }
}

// ---------------------------------------------------------------------------
// CUDA-core adder kernel (R8): S-stage cp.async pipeline, packed f32x2 |b-a|.
//   CONV 0: 1x1 fill   CONV 1: implicit 3x3 (k = c*9+rs order), zfill halo
//   EPI 1: relu(bn(-acc))   EPI 2: relu(bn3(-acc)+resid) NCHW store
// ---------------------------------------------------------------------------
template<int BM, int TM, int BK, int S, int CONV, int EPI,
         int WID, int XID, int YID>
__global__ void __launch_bounds__(128)
gx(float* Yrt, int Mtot, int K,
   const float* __restrict__ bg, const float* __restrict__ bb,
   const float* __restrict__ bm, const float* __restrict__ bv,
   const float* __restrict__ resid)
{
    constexpr int BN = 128, NT = 128;
    static_assert((BM / TM) * 16 == NT, "tile/threads mismatch");
    constexpr int AF4 = BK * BM / 4;
    constexpr int AU  = (AF4 + NT - 1) / NT;
    constexpr int BU  = CONV ? 1 : (BK * BN / 4 / NT);
    const float* Wt = gbuf<WID>(nullptr);
    const float* X  = gbuf<XID>(nullptr);
    float*       Y  = gbuf<YID>(Yrt);

    __shared__ __align__(16) float As[S][BK * BM];
    __shared__ __align__(16) float Bs[S][BK * BN];

    int tid = threadIdx.x;
    int tx  = tid % 16;
    int ty  = tid / 16;
    int m0  = blockIdx.y * BM;
    int n0  = blockIdx.x * BN;

    int cn = n0 + tid;
    int coff[9]; int csz[9];
    if (CONV) {
        int cw = cn % WD;
        int ch = (cn / WD) % WD;
#pragma unroll
        for (int q = 0; q < 9; q++) {
            const int r = q / 3, s = q % 3;
            int hh = ch + r - 1, ww = cw + s - 1;
            bool ok = (hh >= 0 && hh < WD && ww >= 0 && ww < WD);
            coff[q] = ok ? (r - 1) * WD + (s - 1) : 0;
            csz[q]  = ok ? 4 : 0;
        }
    }

    const uint32_t AsU = s2u(&As[0][0]);
    const uint32_t BsU = s2u(&Bs[0][0]);
    constexpr int ASTAGE = BK * BM * 4;
    constexpr int BSTAGE = BK * BN * 4;

    auto fill = [&](int t) {
        int st = t % S;
        int k0 = t * BK;
#pragma unroll
        for (int u = 0; u < AU; u++) {
            int v = tid + u * NT;
            if (AF4 % NT == 0 || v < AF4) {
                int kk = v / (BM / 4), mq = v - kk * (BM / 4);
                cpa16(AsU + st * ASTAGE + (kk * BM + mq * 4) * 4,
                      &Wt[(long)(k0 + kk) * Mtot + m0 + mq * 4]);
            }
        }
        if (CONV == 0) {
#pragma unroll
            for (int u = 0; u < BU; u++) {
                int v = tid + u * NT;
                int kk = v / (BN / 4), nq = v - kk * (BN / 4);
                cpa16(BsU + st * BSTAGE + (kk * BN + nq * 4) * 4,
                      &X[(long)(k0 + kk) * NTOT + n0 + nq * 4]);
            }
        } else {
            int c0 = k0 / 9;
#pragma unroll
            for (int half = 0; half < 2; half++) {
                const float* base = &X[(long)(c0 + half) * NTOT + cn];
#pragma unroll
                for (int q = 0; q < 9; q++)
                    cpa4z(BsU + st * BSTAGE + ((half * 9 + q) * BN + tid) * 4,
                          base + coff[q], csz[q]);
            }
        }
    };

    unsigned long long acc2[TM][4];
#pragma unroll
    for (int i = 0; i < TM; i++)
#pragma unroll
        for (int j = 0; j < 4; j++) acc2[i][j] = 0ULL;

    int T = K / BK;
#pragma unroll
    for (int p = 0; p < S - 1; p++) {
        if (p < T) fill(p);
        cp_commit();
    }

    for (int t = 0; t < T; t++) {
        cp_wait<S - 2>();
        __syncthreads();
        int tf = t + S - 1;
        if (tf < T) fill(tf);
        cp_commit();

        int st = t % S;
#pragma unroll
        for (int kk = 0; kk < BK; kk++) {
            float a[TM];
            *(float4*)&a[0] = *(const float4*)&As[st][kk * BM + ty * TM];
            if constexpr (TM == 8)
                *(float4*)&a[4] = *(const float4*)&As[st][kk * BM + ty * TM + 4];
            unsigned long long ad[TM];
#pragma unroll
            for (int i = 0; i < TM; i++)
                asm("mov.b64 %0, {%1, %1};" : "=l"(ad[i]) : "f"(a[i]));
            unsigned long long b2[4];
            {
                ulonglong2 p0 = *(const ulonglong2*)&Bs[st][kk * BN + tx * 8];
                ulonglong2 p1 = *(const ulonglong2*)&Bs[st][kk * BN + tx * 8 + 4];
                b2[0] = p0.x; b2[1] = p0.y; b2[2] = p1.x; b2[3] = p1.y;
            }
#pragma unroll
            for (int i = 0; i < TM; i++)
#pragma unroll
                for (int jp = 0; jp < 4; jp++) {
                    unsigned long long d;
                    asm("add.rn.f32x2 %0, %1, %2;"
                        : "=l"(d) : "l"(b2[jp]), "l"(ad[i]));
                    d &= 0x7FFFFFFF7FFFFFFFULL;
                    asm("add.rn.f32x2 %0, %0, %1;"
                        : "+l"(acc2[i][jp]) : "l"(d));
                }
        }
    }
    cp_wait<0>();

    float accf[TM][8];
#pragma unroll
    for (int i = 0; i < TM; i++)
#pragma unroll
        for (int jp = 0; jp < 4; jp++)
            asm("mov.b64 {%0, %1}, %2;"
                : "=f"(accf[i][2*jp]), "=f"(accf[i][2*jp+1]) : "l"(acc2[i][jp]));

#pragma unroll
    for (int i = 0; i < TM; i++) {
        int m = m0 + ty * TM + i;
        float inv  = bg[m] * rsqrtf(bv[m] + 1e-5f);
        float bias = bb[m] - bm[m] * inv;
        if (EPI == 2) {
#pragma unroll
            for (int j = 0; j < 8; j++) {
                int n   = n0 + tx * 8 + j;
                int b_  = n / HWSZ;
                int hw  = n - b_ * HWSZ;
                int idx = (b_ * 512 + m) * HWSZ + hw;
                float v = fmaf(accf[i][j], -inv, bias) + resid[idx];
                Y[idx] = fmaxf(v, 0.0f);
            }
        } else {
            float o[8];
#pragma unroll
            for (int j = 0; j < 8; j++)
                o[j] = fmaxf(fmaf(-accf[i][j], inv, bias), 0.0f);
            int base = m * NTOT + n0 + tx * 8;
            *(float4*)&Y[base]     = make_float4(o[0], o[1], o[2], o[3]);
            *(float4*)&Y[base + 4] = make_float4(o[4], o[5], o[6], o[7]);
        }
    }
}

// ---------------------------------------------------------------------------
extern "C" void kernel_launch(void* const* d_in, const int* in_sizes, int n_in,
                              void* d_out, int out_size) {
    const float* x   = (const float*)d_in[0];
    const float* w1s = (const float*)d_in[1];
    const float* w1a = (const float*)d_in[2];
    const float* w2s = (const float*)d_in[3];
    const float* w2a = (const float*)d_in[4];
    const float* w3s = (const float*)d_in[5];
    const float* w3a = (const float*)d_in[6];
    const float* g1 = (const float*)d_in[7],  *b1 = (const float*)d_in[8];
    const float* m1 = (const float*)d_in[9],  *v1 = (const float*)d_in[10];
    const float* g2 = (const float*)d_in[11], *b2 = (const float*)d_in[12];
    const float* m2 = (const float*)d_in[13], *v2 = (const float*)d_in[14];
    const float* g3 = (const float*)d_in[15], *b3 = (const float*)d_in[16];
    const float* m3 = (const float*)d_in[17], *v3 = (const float*)d_in[18];
    float* out = (float*)d_out;

    __nv_bfloat16 *w1bf, *w2bf, *w3bf, *xth, *xtl, *uth, *utl;
    float *tA, *tC;
    cudaGetSymbolAddress((void**)&w1bf, g_w1bf);
    cudaGetSymbolAddress((void**)&w2bf, g_w2bf);
    cudaGetSymbolAddress((void**)&w3bf, g_w3bf);
    cudaGetSymbolAddress((void**)&xth, g_xth);
    cudaGetSymbolAddress((void**)&xtl, g_xtl);
    cudaGetSymbolAddress((void**)&uth, g_uth);
    cudaGetSymbolAddress((void**)&utl, g_utl);
    cudaGetSymbolAddress((void**)&tA, g_A);
    cudaGetSymbolAddress((void**)&tC, g_C);

    wprep_all<<<(704512 + 255) / 256, 256>>>(w1s, w1a, w2s, w2a, w3s, w3a);
    tsplit_x<<<dim3(25, 16, 16), dim3(32, 8)>>>(x);

    dim3 gsm(98, 4);   // adder1/2, BM=32
    dim3 gbg(98, 8);   // adder3, BM=64

    // stage 1: shift 1x1 via mma.sync (K=512, 16 chunks) -> t1 (g_A)
    mma_shift<0><<<dim3(196, 2), 128>>>(w1bf, xth, xtl, tA, 128, 512, 512, 16);
    // stage 1: adder 1x1 + BN1 + ReLU -> u1 (g_B)
    gx<32,4,16,4, 0,1, 5,1,2><<<gsm,128>>>(
        nullptr, 128, 128, g1, b1, m1, v1, nullptr);

    // split/transpose u1 -> ut planes
    tsplit_u<<<dim3(392, 4), dim3(32, 8)>>>();
    // stage 2: shift 3x3 via mma.sync (36 chunks, rs-major K) -> t2 (g_C)
    mma_shift<1><<<dim3(196, 2), 128>>>(w2bf, uth, utl, tC, 128, 1152, 128, 36);
    // stage 2: adder 3x3 + BN2 + ReLU -> u2 (g_B)
    gx<32,4,18,4, 1,1, 7,3,2><<<gsm,128>>>(
        nullptr, 128, 1152, g2, b2, m2, v2, nullptr);

    // split/transpose u2 -> ut planes
    tsplit_u<<<dim3(392, 4), dim3(32, 8)>>>();
    // stage 3: shift 1x1 via mma.sync (M=512, K=128, 4 chunks) -> t3 (g_A)
    mma_shift<0><<<dim3(196, 8), 128>>>(w3bf, uth, utl, tA, 512, 128, 128, 4);
    // stage 3: adder 1x1 (K=512) + BN3 + resid + ReLU -> out (NCHW)
    gx<64,8,16,3, 0,2, 9,1,-1><<<gbg,128>>>(
        out, 512, 512, g3, b3, m3, v3, x);
}